// round 11
// baseline (speedup 1.0000x reference)
#include <cuda_runtime.h>
#include <cuda_fp16.h>
#include <cstdint>

#define NTOK 8192
#define DIM  1024
#define NEXP 8
#define HID  4096
#define PADTOK (NTOK + 128)

// ===================== helpers =====================
__device__ __forceinline__ uint32_t smem_u32(const void* p) {
    uint32_t a;
    asm("{ .reg .u64 t; cvta.to.shared.u64 t, %1; cvt.u32.u64 %0, t; }" : "=r"(a) : "l"(p));
    return a;
}
__device__ __forceinline__ void cp16(uint32_t dst, const void* src) {
    asm volatile("cp.async.cg.shared.global [%0], [%1], 16;" :: "r"(dst), "l"(src) : "memory");
}
#define CP_COMMIT() asm volatile("cp.async.commit_group;" ::: "memory")
#define CP_WAIT2()  asm volatile("cp.async.wait_group 2;" ::: "memory")

__device__ __forceinline__ void ldsm4(uint32_t& r0, uint32_t& r1, uint32_t& r2, uint32_t& r3,
                                      uint32_t addr) {
    asm volatile("ldmatrix.sync.aligned.m8n8.x4.shared.b16 {%0,%1,%2,%3}, [%4];"
                 : "=r"(r0), "=r"(r1), "=r"(r2), "=r"(r3) : "r"(addr));
}
__device__ __forceinline__ void mma16816(float& c0, float& c1, float& c2, float& c3,
                                         uint32_t a0, uint32_t a1, uint32_t a2, uint32_t a3,
                                         uint32_t b0, uint32_t b1) {
    asm volatile(
        "mma.sync.aligned.m16n8k16.row.col.f32.f16.f16.f32 "
        "{%0,%1,%2,%3}, {%4,%5,%6,%7}, {%8,%9}, {%0,%1,%2,%3};"
        : "+f"(c0), "+f"(c1), "+f"(c2), "+f"(c3)
        : "r"(a0), "r"(a1), "r"(a2), "r"(a3), "r"(b0), "r"(b1));
}

// ===================== device scratch =====================
__device__ int g_top1[NTOK];
__device__ int g_cnt[NEXP];
__device__ int g_cnt2[NEXP];
__device__ int g_off[NEXP];
__device__ int g_perm[NTOK];

__device__ __half g_x16[(size_t)NTOK * DIM];        // x fp16, TOKEN order
__device__ __half g_h[(size_t)PADTOK * HID];        // hidden, fp16, slot order
__device__ __half g_w1[(size_t)NEXP * HID * DIM];   // [e][n(HID)][k(DIM)]
__device__ __half g_w2[(size_t)NEXP * DIM * HID];   // [e][n(DIM)][k(HID)]

// ===================== conv tile body (32x32 transpose fp32->fp16) =====================
__device__ __forceinline__ void conv_tile(const float* __restrict__ src, __half* __restrict__ dst,
                                          int R, int C, int e, int r0, int c0) {
    __shared__ float tile[32][33];
    const int tx = threadIdx.x & 31;
    const int ty = threadIdx.x >> 5;   // 0..7
    const float* s = src + ((size_t)e * R + r0) * C + c0;
#pragma unroll
    for (int j = ty; j < 32; j += 8)
        tile[j][tx] = s[(size_t)j * C + tx];
    __syncthreads();
    __half* o = dst + ((size_t)e * C + c0) * R + r0;
#pragma unroll
    for (int j = ty; j < 32; j += 8)
        o[(size_t)j * R + tx] = __float2half_rn(tile[tx][j]);
}

// ===================== launch 0: gate (+x16) + conv_w1 + conv_w2 =====================
__global__ __launch_bounds__(256)
void gate_conv_kernel(const float* __restrict__ x,
                      const float* __restrict__ gw,
                      const float* __restrict__ gb,
                      const float* __restrict__ w1,
                      const float* __restrict__ w2) {
    const int b = blockIdx.x;
    if (b >= 1024 + 32768) {
        int cb = b - 1024 - 32768;         // conv_w2
        int e  = cb >> 12;
        int r  = cb & 4095;
        int c0 = (r & 31) * 32;
        int r0 = (r >> 5) * 32;
        conv_tile(w2, g_w2, HID, DIM, e, r0, c0);
        return;
    }
    if (b >= 1024) {
        int cb = b - 1024;                 // conv_w1
        int e  = cb >> 12;
        int r  = cb & 4095;
        int c0 = (r & 127) * 32;
        int r0 = (r >> 7) * 32;
        conv_tile(w1, g_w1, DIM, HID, e, r0, c0);
        return;
    }
    int wid  = threadIdx.x >> 5;
    int lane = threadIdx.x & 31;
    int tok  = b * 8 + wid;
    const float* xr = x + (size_t)tok * DIM;
    __half* xo = g_x16 + (size_t)tok * DIM;
    float acc[NEXP];
#pragma unroll
    for (int e = 0; e < NEXP; e++) acc[e] = 0.f;
    for (int d0 = lane * 4; d0 < DIM; d0 += 128) {
        float4 v = *reinterpret_cast<const float4*>(xr + d0);
        reinterpret_cast<__half2*>(xo + d0)[0] = __floats2half2_rn(v.x, v.y);
        reinterpret_cast<__half2*>(xo + d0)[1] = __floats2half2_rn(v.z, v.w);
        const float* g0 = gw + (size_t)d0 * NEXP;
#pragma unroll
        for (int dd = 0; dd < 4; dd++) {
            float xv = (dd == 0) ? v.x : (dd == 1) ? v.y : (dd == 2) ? v.z : v.w;
            const float4* g4 = reinterpret_cast<const float4*>(g0 + dd * NEXP);
            float4 a = g4[0], bq = g4[1];
            acc[0] += xv * a.x;  acc[1] += xv * a.y;  acc[2] += xv * a.z;  acc[3] += xv * a.w;
            acc[4] += xv * bq.x; acc[5] += xv * bq.y; acc[6] += xv * bq.z; acc[7] += xv * bq.w;
        }
    }
#pragma unroll
    for (int e = 0; e < NEXP; e++) {
#pragma unroll
        for (int o = 16; o > 0; o >>= 1) acc[e] += __shfl_xor_sync(0xffffffffu, acc[e], o);
    }
    if (lane == 0) {
        int best = 0; float bv = acc[0] + gb[0];
#pragma unroll
        for (int e = 1; e < NEXP; e++) {
            float v = acc[e] + gb[e];
            if (v > bv) { bv = v; best = e; }
        }
        g_top1[tok] = best;
    }
}

// ===================== launch 1: histogram + scan (1 block) =====================
__global__ void hist_kernel() {
    __shared__ int cnt[NEXP];
    const int tid = threadIdx.x;
    if (tid < NEXP) cnt[tid] = 0;
    __syncthreads();
    int local[NEXP];
#pragma unroll
    for (int e = 0; e < NEXP; e++) local[e] = 0;
    for (int i = tid; i < NTOK; i += 1024) {
        int v = g_top1[i];
#pragma unroll
        for (int e = 0; e < NEXP; e++) local[e] += (v == e);
    }
#pragma unroll
    for (int e = 0; e < NEXP; e++) {
#pragma unroll
        for (int o = 16; o > 0; o >>= 1) local[e] += __shfl_xor_sync(0xffffffffu, local[e], o);
        if ((tid & 31) == 0 && local[e]) atomicAdd(&cnt[e], local[e]);
    }
    __syncthreads();
    if (tid == 0) {
        int off = 0;
        for (int e = 0; e < NEXP; e++) { g_off[e] = off; g_cnt[e] = cnt[e]; off += cnt[e]; }
    }
    if (tid < NEXP) g_cnt2[tid] = 0;
}

// ===================== launch 2: scatter =====================
__global__ __launch_bounds__(256)
void scatter_kernel() {
    int n = blockIdx.x * 256 + threadIdx.x;
    int e = g_top1[n];
    int p = atomicAdd(&g_cnt2[e], 1);
    g_perm[g_off[e] + p] = n;
}

// ===================== GEMM core: CTA 128x128, 4 warps 2x2, warp tile 64x64 =====================
#define AOFF 0
#define BOFF 16384
#define STAGE 32768
#define NSTAGE 3

template<bool FIRST>
__global__ __launch_bounds__(128, 2)
void moe_gemm(const float* __restrict__ bias,
              const float* __restrict__ x,
              float* __restrict__ out) {
    constexpr int KDIM = FIRST ? DIM : HID;
    constexpr int NDIM = FIRST ? HID : DIM;
    constexpr int NKC  = KDIM / 64;

    const int e  = blockIdx.z;
    const int Me = g_cnt[e];
    const int m0 = blockIdx.y * 128;
    if (m0 >= Me) return;
    const int off = g_off[e];
    const int n0  = blockIdx.x * 128;

    const __half* A = FIRST ? g_x16 : g_h;
    const __half* W = (FIRST ? g_w1 : g_w2) + (size_t)e * NDIM * KDIM;

    extern __shared__ char smem[];
    const uint32_t sb = smem_u32(smem);
    __shared__ int s_perm[128];

    const int tid  = threadIdx.x;
    const int lane = tid & 31;
    const int wid  = tid >> 5;
    const int wrow = wid & 1;
    const int wcol = wid >> 1;

    {
        int r = m0 + tid;
        if (r >= Me) r = Me - 1;
        s_perm[tid] = g_perm[off + r];
    }
    __syncthreads();

    auto issue_loads = [&](int chunk) {
        const uint32_t base = sb + (chunk % NSTAGE) * STAGE;
        const int k0 = chunk * 64;
#pragma unroll
        for (int w = 0; w < 8; w++) {
            int idx = w * 128 + tid;
            int row = idx >> 3;
            int c8  = idx & 7;
            uint32_t sw = (uint32_t)(row * 128 + ((c8 * 16) ^ ((row & 7) << 4)));
            const __half* asrc;
            if (FIRST) asrc = A + (size_t)s_perm[row] * KDIM + k0 + c8 * 8;
            else       asrc = A + (size_t)(off + m0 + row) * KDIM + k0 + c8 * 8;
            cp16(base + AOFF + sw, asrc);
            cp16(base + BOFF + sw, W + (size_t)(n0 + row) * KDIM + k0 + c8 * 8);
        }
    };

    const int sel = lane >> 3;
    const int l7  = lane & 7;
    const uint32_t lxor = (uint32_t)(l7 << 4);
    uint32_t arow[4], brow[4];
#pragma unroll
    for (int mf = 0; mf < 4; mf++)
        arow[mf] = (uint32_t)((wrow * 64 + mf * 16 + (sel & 1) * 8 + l7) * 128);
#pragma unroll
    for (int nb = 0; nb < 4; nb++)
        brow[nb] = (uint32_t)((wcol * 64 + nb * 16 + (sel >> 1) * 8 + l7) * 128);
    const uint32_t acb = (uint32_t)((sel >> 1) * 16);
    const uint32_t bcb = (uint32_t)((sel & 1) * 16);

    float c[4][8][4];
#pragma unroll
    for (int i = 0; i < 4; i++)
#pragma unroll
        for (int j = 0; j < 8; j++)
#pragma unroll
            for (int r = 0; r < 4; r++) c[i][j][r] = 0.f;

    issue_loads(0); CP_COMMIT();
    issue_loads(1); CP_COMMIT();

    for (int i = 0; i < NKC; i++) {
        if (i + 2 < NKC) issue_loads(i + 2);
        CP_COMMIT();
        CP_WAIT2();
        __syncthreads();

        const uint32_t base = sb + (i % NSTAGE) * STAGE;
#pragma unroll
        for (int kk = 0; kk < 4; kk++) {
            const uint32_t colA = (acb + kk * 32) ^ lxor;
            const uint32_t colB = (bcb + kk * 32) ^ lxor;

            uint32_t Af[4][4], Bf[4][4];
#pragma unroll
            for (int mf = 0; mf < 4; mf++)
                ldsm4(Af[mf][0], Af[mf][1], Af[mf][2], Af[mf][3], base + AOFF + arow[mf] + colA);
#pragma unroll
            for (int nb = 0; nb < 4; nb++)
                ldsm4(Bf[nb][0], Bf[nb][1], Bf[nb][2], Bf[nb][3], base + BOFF + brow[nb] + colB);
#pragma unroll
            for (int mf = 0; mf < 4; mf++)
#pragma unroll
                for (int nb = 0; nb < 4; nb++)
#pragma unroll
                    for (int h = 0; h < 2; h++)
                        mma16816(c[mf][nb*2+h][0], c[mf][nb*2+h][1], c[mf][nb*2+h][2], c[mf][nb*2+h][3],
                                 Af[mf][0], Af[mf][1], Af[mf][2], Af[mf][3],
                                 Bf[nb][2*h], Bf[nb][2*h+1]);
        }
        __syncthreads();
    }

    const int gr = lane >> 2;
    const int gc = (lane & 3) * 2;
    const float* bs = bias + (size_t)e * NDIM;

#pragma unroll
    for (int mf = 0; mf < 4; mf++) {
#pragma unroll
        for (int half = 0; half < 2; half++) {
            const int ml = wrow * 64 + mf * 16 + half * 8 + gr;
            if (m0 + ml >= Me) continue;
            const int slot = off + m0 + ml;
#pragma unroll
            for (int nf = 0; nf < 8; nf++) {
                const int n = n0 + wcol * 64 + nf * 8 + gc;
                const float2 bv = *reinterpret_cast<const float2*>(bs + n);
                float v0 = c[mf][nf][half * 2 + 0] + bv.x;
                float v1 = c[mf][nf][half * 2 + 1] + bv.y;
                if (FIRST) {
                    v0 = fmaxf(v0, 0.f);
                    v1 = fmaxf(v1, 0.f);
                    *reinterpret_cast<__half2*>(g_h + (size_t)slot * HID + n) =
                        __half2(__float2half_rn(v0), __float2half_rn(v1));
                } else {
                    const int tok = s_perm[ml];
                    const float2 xv = *reinterpret_cast<const float2*>(x + (size_t)tok * DIM + n);
                    float2 ov = make_float2(v0 + xv.x, v1 + xv.y);
                    *reinterpret_cast<float2*>(out + (size_t)tok * DIM + n) = ov;
                }
            }
        }
    }
}

// ===================== launch =====================
extern "C" void kernel_launch(void* const* d_in, const int* in_sizes, int n_in,
                              void* d_out, int out_size) {
    const float* x  = (const float*)d_in[0];
    const float* gw = (const float*)d_in[1];
    const float* gb = (const float*)d_in[2];
    const float* w1 = (const float*)d_in[3];
    const float* b1 = (const float*)d_in[4];
    const float* w2 = (const float*)d_in[5];
    const float* b2 = (const float*)d_in[6];
    float* out = (float*)d_out;

    const int SMEM_BYTES = NSTAGE * STAGE;   // 96KB -> 2 CTAs/SM
    cudaFuncSetAttribute(moe_gemm<true>,  cudaFuncAttributeMaxDynamicSharedMemorySize, SMEM_BYTES);
    cudaFuncSetAttribute(moe_gemm<false>, cudaFuncAttributeMaxDynamicSharedMemorySize, SMEM_BYTES);

    // launch 0: gate + conv_w1 + conv_w2 (all independent)
    gate_conv_kernel<<<1024 + 2 * 32768, 256>>>(x, gw, gb, w1, w2);
    // launch 1: histogram + scan
    hist_kernel<<<1, 1024>>>();
    // launch 2: scatter
    scatter_kernel<<<NTOK / 256, 256>>>();
    // launch 3: GEMM1
    moe_gemm<true ><<<dim3(HID / 128, NTOK / 128, NEXP), 128, SMEM_BYTES>>>(b1, x, nullptr);
    // launch 4: GEMM2
    moe_gemm<false><<<dim3(DIM / 128, NTOK / 128, NEXP), 128, SMEM_BYTES>>>(b2, x, out);
}

// round 12
// speedup vs baseline: 1.0226x; 1.0226x over previous
#include <cuda_runtime.h>
#include <cuda_fp16.h>
#include <cstdint>

#define NTOK 8192
#define DIM  1024
#define NEXP 8
#define HID  4096
#define PADTOK (NTOK + 128)

// ===================== helpers =====================
__device__ __forceinline__ uint32_t smem_u32(const void* p) {
    uint32_t a;
    asm("{ .reg .u64 t; cvta.to.shared.u64 t, %1; cvt.u32.u64 %0, t; }" : "=r"(a) : "l"(p));
    return a;
}
__device__ __forceinline__ void cp16(uint32_t dst, const void* src) {
    asm volatile("cp.async.cg.shared.global [%0], [%1], 16;" :: "r"(dst), "l"(src) : "memory");
}
#define CP_COMMIT() asm volatile("cp.async.commit_group;" ::: "memory")
#define CP_WAIT2()  asm volatile("cp.async.wait_group 2;" ::: "memory")

__device__ __forceinline__ void ldsm4(uint32_t& r0, uint32_t& r1, uint32_t& r2, uint32_t& r3,
                                      uint32_t addr) {
    asm volatile("ldmatrix.sync.aligned.m8n8.x4.shared.b16 {%0,%1,%2,%3}, [%4];"
                 : "=r"(r0), "=r"(r1), "=r"(r2), "=r"(r3) : "r"(addr));
}
__device__ __forceinline__ void mma16816(float& c0, float& c1, float& c2, float& c3,
                                         uint32_t a0, uint32_t a1, uint32_t a2, uint32_t a3,
                                         uint32_t b0, uint32_t b1) {
    asm volatile(
        "mma.sync.aligned.m16n8k16.row.col.f32.f16.f16.f32 "
        "{%0,%1,%2,%3}, {%4,%5,%6,%7}, {%8,%9}, {%0,%1,%2,%3};"
        : "+f"(c0), "+f"(c1), "+f"(c2), "+f"(c3)
        : "r"(a0), "r"(a1), "r"(a2), "r"(a3), "r"(b0), "r"(b1));
}

// ===================== device scratch =====================
__device__ int g_top1[NTOK];
__device__ int g_cnt[NEXP];
__device__ int g_cnt2[NEXP];
__device__ int g_off[NEXP];
__device__ int g_perm[NTOK];

__device__ __half g_x16[(size_t)NTOK * DIM];        // x fp16, TOKEN order
__device__ __half g_h[(size_t)PADTOK * HID];        // hidden, fp16, slot order
__device__ __half g_w1[(size_t)NEXP * HID * DIM];   // [e][n(HID)][k(DIM)]
__device__ __half g_w2[(size_t)NEXP * DIM * HID];   // [e][n(DIM)][k(HID)]

// ===================== conv tile body (32x32 transpose fp32->fp16) =====================
__device__ __forceinline__ void conv_tile(const float* __restrict__ src, __half* __restrict__ dst,
                                          int R, int C, int e, int r0, int c0) {
    __shared__ float tile[32][33];
    const int tx = threadIdx.x & 31;
    const int ty = threadIdx.x >> 5;   // 0..7
    const float* s = src + ((size_t)e * R + r0) * C + c0;
#pragma unroll
    for (int j = ty; j < 32; j += 8)
        tile[j][tx] = s[(size_t)j * C + tx];
    __syncthreads();
    __half* o = dst + ((size_t)e * C + c0) * R + r0;
#pragma unroll
    for (int j = ty; j < 32; j += 8)
        o[(size_t)j * R + tx] = __float2half_rn(tile[tx][j]);
}

// ===================== launch 0: gate (+x16) fused with conv_w1 =====================
// blocks [0,1024): gate; blocks [1024, 1024+32768): conv_w1 tiles
__global__ __launch_bounds__(256)
void gate_convw1_kernel(const float* __restrict__ x,
                        const float* __restrict__ gw,
                        const float* __restrict__ gb,
                        const float* __restrict__ w1) {
    const int b = blockIdx.x;
    if (b >= 1024) {
        int cb = b - 1024;                 // 0..32767
        int e  = cb >> 12;
        int r  = cb & 4095;
        int c0 = (r & 127) * 32;           // HID tile col
        int r0 = (r >> 7) * 32;            // DIM tile row
        conv_tile(w1, g_w1, DIM, HID, e, r0, c0);
        return;
    }
    int wid  = threadIdx.x >> 5;
    int lane = threadIdx.x & 31;
    int tok  = b * 8 + wid;
    const float* xr = x + (size_t)tok * DIM;
    __half* xo = g_x16 + (size_t)tok * DIM;
    float acc[NEXP];
#pragma unroll
    for (int e = 0; e < NEXP; e++) acc[e] = 0.f;
    for (int d0 = lane * 4; d0 < DIM; d0 += 128) {
        float4 v = *reinterpret_cast<const float4*>(xr + d0);
        // coalesced fp16 writes (8B per lane, contiguous across warp)
        reinterpret_cast<__half2*>(xo + d0)[0] = __floats2half2_rn(v.x, v.y);
        reinterpret_cast<__half2*>(xo + d0)[1] = __floats2half2_rn(v.z, v.w);
        const float* g0 = gw + (size_t)d0 * NEXP;
#pragma unroll
        for (int dd = 0; dd < 4; dd++) {
            float xv = (dd == 0) ? v.x : (dd == 1) ? v.y : (dd == 2) ? v.z : v.w;
            const float4* g4 = reinterpret_cast<const float4*>(g0 + dd * NEXP);
            float4 a = g4[0], bq = g4[1];
            acc[0] += xv * a.x;  acc[1] += xv * a.y;  acc[2] += xv * a.z;  acc[3] += xv * a.w;
            acc[4] += xv * bq.x; acc[5] += xv * bq.y; acc[6] += xv * bq.z; acc[7] += xv * bq.w;
        }
    }
#pragma unroll
    for (int e = 0; e < NEXP; e++) {
#pragma unroll
        for (int o = 16; o > 0; o >>= 1) acc[e] += __shfl_xor_sync(0xffffffffu, acc[e], o);
    }
    if (lane == 0) {
        int best = 0; float bv = acc[0] + gb[0];
#pragma unroll
        for (int e = 1; e < NEXP; e++) {
            float v = acc[e] + gb[e];
            if (v > bv) { bv = v; best = e; }
        }
        g_top1[tok] = best;
    }
}

// ===================== launch 1: histogram + scan (1 block) =====================
__global__ void hist_kernel() {
    __shared__ int cnt[NEXP];
    const int tid = threadIdx.x;
    if (tid < NEXP) cnt[tid] = 0;
    __syncthreads();
    int local[NEXP];
#pragma unroll
    for (int e = 0; e < NEXP; e++) local[e] = 0;
    for (int i = tid; i < NTOK; i += 1024) {
        int v = g_top1[i];
#pragma unroll
        for (int e = 0; e < NEXP; e++) local[e] += (v == e);
    }
#pragma unroll
    for (int e = 0; e < NEXP; e++) {
#pragma unroll
        for (int o = 16; o > 0; o >>= 1) local[e] += __shfl_xor_sync(0xffffffffu, local[e], o);
        if ((tid & 31) == 0 && local[e]) atomicAdd(&cnt[e], local[e]);
    }
    __syncthreads();
    if (tid == 0) {
        int off = 0;
        for (int e = 0; e < NEXP; e++) { g_off[e] = off; g_cnt[e] = cnt[e]; off += cnt[e]; }
    }
    if (tid < NEXP) g_cnt2[tid] = 0;
}

// ===================== launch 2: scatter fused with conv_w2 =====================
// blocks [0,32): scatter; blocks [32, 32+32768): conv_w2 tiles
__global__ __launch_bounds__(256)
void scatter_convw2_kernel(const float* __restrict__ w2) {
    const int b = blockIdx.x;
    if (b >= 32) {
        int cb = b - 32;
        int e  = cb >> 12;
        int r  = cb & 4095;
        int c0 = (r & 31) * 32;            // DIM tile col
        int r0 = (r >> 5) * 32;            // HID tile row
        conv_tile(w2, g_w2, HID, DIM, e, r0, c0);
        return;
    }
    int n = b * 256 + threadIdx.x;
    int e = g_top1[n];
    int p = atomicAdd(&g_cnt2[e], 1);
    g_perm[g_off[e] + p] = n;
}

// ===================== GEMM core: CTA 128x128, 4 warps 2x2, warp tile 64x64 =====================
#define AOFF 0
#define BOFF 16384
#define STAGE 32768
#define NSTAGE 3

template<bool FIRST>
__global__ __launch_bounds__(128, 2)
void moe_gemm(const float* __restrict__ bias,
              const float* __restrict__ x,
              float* __restrict__ out) {
    constexpr int KDIM = FIRST ? DIM : HID;
    constexpr int NDIM = FIRST ? HID : DIM;
    constexpr int NKC  = KDIM / 64;

    const int e  = blockIdx.z;
    const int Me = g_cnt[e];
    const int m0 = blockIdx.y * 128;
    if (m0 >= Me) return;
    const int off = g_off[e];
    const int n0  = blockIdx.x * 128;

    const __half* A = FIRST ? g_x16 : g_h;
    const __half* W = (FIRST ? g_w1 : g_w2) + (size_t)e * NDIM * KDIM;

    extern __shared__ char smem[];
    const uint32_t sb = smem_u32(smem);
    __shared__ int s_perm[128];

    const int tid  = threadIdx.x;
    const int lane = tid & 31;
    const int wid  = tid >> 5;
    const int wrow = wid & 1;
    const int wcol = wid >> 1;

    {
        int r = m0 + tid;
        if (r >= Me) r = Me - 1;
        s_perm[tid] = g_perm[off + r];
    }
    __syncthreads();

    auto issue_loads = [&](int chunk) {
        const uint32_t base = sb + (chunk % NSTAGE) * STAGE;
        const int k0 = chunk * 64;
#pragma unroll
        for (int w = 0; w < 8; w++) {
            int idx = w * 128 + tid;
            int row = idx >> 3;
            int c8  = idx & 7;
            uint32_t sw = (uint32_t)(row * 128 + ((c8 * 16) ^ ((row & 7) << 4)));
            const __half* asrc;
            if (FIRST) asrc = A + (size_t)s_perm[row] * KDIM + k0 + c8 * 8;
            else       asrc = A + (size_t)(off + m0 + row) * KDIM + k0 + c8 * 8;
            cp16(base + AOFF + sw, asrc);
            cp16(base + BOFF + sw, W + (size_t)(n0 + row) * KDIM + k0 + c8 * 8);
        }
    };

    const int sel = lane >> 3;
    const int l7  = lane & 7;
    const uint32_t lxor = (uint32_t)(l7 << 4);
    uint32_t arow[4], brow[4];
#pragma unroll
    for (int mf = 0; mf < 4; mf++)
        arow[mf] = (uint32_t)((wrow * 64 + mf * 16 + (sel & 1) * 8 + l7) * 128);
#pragma unroll
    for (int nb = 0; nb < 4; nb++)
        brow[nb] = (uint32_t)((wcol * 64 + nb * 16 + (sel >> 1) * 8 + l7) * 128);
    const uint32_t acb = (uint32_t)((sel >> 1) * 16);
    const uint32_t bcb = (uint32_t)((sel & 1) * 16);

    float c[4][8][4];
#pragma unroll
    for (int i = 0; i < 4; i++)
#pragma unroll
        for (int j = 0; j < 8; j++)
#pragma unroll
            for (int r = 0; r < 4; r++) c[i][j][r] = 0.f;

    issue_loads(0); CP_COMMIT();
    issue_loads(1); CP_COMMIT();

    for (int i = 0; i < NKC; i++) {
        if (i + 2 < NKC) issue_loads(i + 2);
        CP_COMMIT();
        CP_WAIT2();
        __syncthreads();

        const uint32_t base = sb + (i % NSTAGE) * STAGE;
#pragma unroll
        for (int kk = 0; kk < 4; kk++) {
            const uint32_t colA = (acb + kk * 32) ^ lxor;
            const uint32_t colB = (bcb + kk * 32) ^ lxor;

            uint32_t Af[4][4], Bf[4][4];
#pragma unroll
            for (int mf = 0; mf < 4; mf++)
                ldsm4(Af[mf][0], Af[mf][1], Af[mf][2], Af[mf][3], base + AOFF + arow[mf] + colA);
#pragma unroll
            for (int nb = 0; nb < 4; nb++)
                ldsm4(Bf[nb][0], Bf[nb][1], Bf[nb][2], Bf[nb][3], base + BOFF + brow[nb] + colB);
#pragma unroll
            for (int mf = 0; mf < 4; mf++)
#pragma unroll
                for (int nb = 0; nb < 4; nb++)
#pragma unroll
                    for (int h = 0; h < 2; h++)
                        mma16816(c[mf][nb*2+h][0], c[mf][nb*2+h][1], c[mf][nb*2+h][2], c[mf][nb*2+h][3],
                                 Af[mf][0], Af[mf][1], Af[mf][2], Af[mf][3],
                                 Bf[nb][2*h], Bf[nb][2*h+1]);
        }
        __syncthreads();
    }

    const int gr = lane >> 2;
    const int gc = (lane & 3) * 2;
    const float* bs = bias + (size_t)e * NDIM;

#pragma unroll
    for (int mf = 0; mf < 4; mf++) {
#pragma unroll
        for (int half = 0; half < 2; half++) {
            const int ml = wrow * 64 + mf * 16 + half * 8 + gr;
            if (m0 + ml >= Me) continue;
            const int slot = off + m0 + ml;
#pragma unroll
            for (int nf = 0; nf < 8; nf++) {
                const int n = n0 + wcol * 64 + nf * 8 + gc;
                const float2 bv = *reinterpret_cast<const float2*>(bs + n);
                float v0 = c[mf][nf][half * 2 + 0] + bv.x;
                float v1 = c[mf][nf][half * 2 + 1] + bv.y;
                if (FIRST) {
                    v0 = fmaxf(v0, 0.f);
                    v1 = fmaxf(v1, 0.f);
                    *reinterpret_cast<__half2*>(g_h + (size_t)slot * HID + n) =
                        __half2(__float2half_rn(v0), __float2half_rn(v1));
                } else {
                    const int tok = s_perm[ml];
                    const float2 xv = *reinterpret_cast<const float2*>(x + (size_t)tok * DIM + n);
                    float2 ov = make_float2(v0 + xv.x, v1 + xv.y);
                    *reinterpret_cast<float2*>(out + (size_t)tok * DIM + n) = ov;
                }
            }
        }
    }
}

// ===================== launch =====================
extern "C" void kernel_launch(void* const* d_in, const int* in_sizes, int n_in,
                              void* d_out, int out_size) {
    const float* x  = (const float*)d_in[0];
    const float* gw = (const float*)d_in[1];
    const float* gb = (const float*)d_in[2];
    const float* w1 = (const float*)d_in[3];
    const float* b1 = (const float*)d_in[4];
    const float* w2 = (const float*)d_in[5];
    const float* b2 = (const float*)d_in[6];
    float* out = (float*)d_out;

    const int SMEM_BYTES = NSTAGE * STAGE;   // 96KB -> 2 CTAs/SM
    cudaFuncSetAttribute(moe_gemm<true>,  cudaFuncAttributeMaxDynamicSharedMemorySize, SMEM_BYTES);
    cudaFuncSetAttribute(moe_gemm<false>, cudaFuncAttributeMaxDynamicSharedMemorySize, SMEM_BYTES);

    // launch 0: gate + conv_w1 (independent blocks, run concurrently)
    gate_convw1_kernel<<<1024 + 32768, 256>>>(x, gw, gb, w1);
    // launch 1: histogram + scan
    hist_kernel<<<1, 1024>>>();
    // launch 2: scatter + conv_w2
    scatter_convw2_kernel<<<32 + 32768, 256>>>(w2);
    // launch 3: GEMM1
    moe_gemm<true ><<<dim3(HID / 128, NTOK / 128, NEXP), 128, SMEM_BYTES>>>(b1, x, nullptr);
    // launch 4: GEMM2
    moe_gemm<false><<<dim3(DIM / 128, NTOK / 128, NEXP), 128, SMEM_BYTES>>>(b2, x, out);
}

// round 13
// speedup vs baseline: 1.0919x; 1.0677x over previous
#include <cuda_runtime.h>
#include <cuda_fp16.h>
#include <cstdint>

#define NTOK 8192
#define DIM  1024
#define NEXP 8
#define HID  4096
#define PADTOK (NTOK + 128)

// ===================== helpers =====================
__device__ __forceinline__ uint32_t smem_u32(const void* p) {
    uint32_t a;
    asm("{ .reg .u64 t; cvta.to.shared.u64 t, %1; cvt.u32.u64 %0, t; }" : "=r"(a) : "l"(p));
    return a;
}
__device__ __forceinline__ void cp16(uint32_t dst, const void* src) {
    asm volatile("cp.async.cg.shared.global [%0], [%1], 16;" :: "r"(dst), "l"(src) : "memory");
}
#define CP_COMMIT() asm volatile("cp.async.commit_group;" ::: "memory")
#define CP_WAIT1()  asm volatile("cp.async.wait_group 1;" ::: "memory")
#define CP_WAIT0()  asm volatile("cp.async.wait_group 0;" ::: "memory")

__device__ __forceinline__ void ldsm4(uint32_t& r0, uint32_t& r1, uint32_t& r2, uint32_t& r3,
                                      uint32_t addr) {
    asm volatile("ldmatrix.sync.aligned.m8n8.x4.shared.b16 {%0,%1,%2,%3}, [%4];"
                 : "=r"(r0), "=r"(r1), "=r"(r2), "=r"(r3) : "r"(addr));
}
__device__ __forceinline__ void mma16816(float& c0, float& c1, float& c2, float& c3,
                                         uint32_t a0, uint32_t a1, uint32_t a2, uint32_t a3,
                                         uint32_t b0, uint32_t b1) {
    asm volatile(
        "mma.sync.aligned.m16n8k16.row.col.f32.f16.f16.f32 "
        "{%0,%1,%2,%3}, {%4,%5,%6,%7}, {%8,%9}, {%0,%1,%2,%3};"
        : "+f"(c0), "+f"(c1), "+f"(c2), "+f"(c3)
        : "r"(a0), "r"(a1), "r"(a2), "r"(a3), "r"(b0), "r"(b1));
}

// ===================== device scratch =====================
__device__ int g_top1[NTOK];
__device__ int g_cnt[NEXP];
__device__ int g_cnt2[NEXP];
__device__ int g_off[NEXP];
__device__ int g_perm[NTOK];

__device__ __half g_x16[(size_t)NTOK * DIM];        // x fp16, TOKEN order
__device__ __half g_h[(size_t)PADTOK * HID];        // hidden, fp16, slot order
__device__ __half g_w1[(size_t)NEXP * HID * DIM];   // [e][n(HID)][k(DIM)]
__device__ __half g_w2[(size_t)NEXP * DIM * HID];   // [e][n(DIM)][k(HID)]

// ===================== conv tile body (32x32 transpose fp32->fp16) =====================
__device__ __forceinline__ void conv_tile(const float* __restrict__ src, __half* __restrict__ dst,
                                          int R, int C, int e, int r0, int c0) {
    __shared__ float tile[32][33];
    const int tx = threadIdx.x & 31;
    const int ty = threadIdx.x >> 5;   // 0..7
    const float* s = src + ((size_t)e * R + r0) * C + c0;
#pragma unroll
    for (int j = ty; j < 32; j += 8)
        tile[j][tx] = s[(size_t)j * C + tx];
    __syncthreads();
    __half* o = dst + ((size_t)e * C + c0) * R + r0;
#pragma unroll
    for (int j = ty; j < 32; j += 8)
        o[(size_t)j * R + tx] = __float2half_rn(tile[tx][j]);
}

// ===================== launch 0: gate (+x16) fused with conv_w1 (R9-exact) ==========
// blocks [0,1024): gate; blocks [1024, 1024+32768): conv_w1 tiles
__global__ __launch_bounds__(256)
void gate_convw1_kernel(const float* __restrict__ x,
                        const float* __restrict__ gw,
                        const float* __restrict__ gb,
                        const float* __restrict__ w1) {
    const int b = blockIdx.x;
    if (b >= 1024) {
        int cb = b - 1024;                 // 0..32767
        int e  = cb >> 12;
        int r  = cb & 4095;
        int c0 = (r & 127) * 32;           // HID tile col
        int r0 = (r >> 7) * 32;            // DIM tile row
        conv_tile(w1, g_w1, DIM, HID, e, r0, c0);
        return;
    }
    int wid  = threadIdx.x >> 5;
    int lane = threadIdx.x & 31;
    int tok  = b * 8 + wid;
    const float* xr = x + (size_t)tok * DIM;
    __half* xo = g_x16 + (size_t)tok * DIM;
    float acc[NEXP];
#pragma unroll
    for (int e = 0; e < NEXP; e++) acc[e] = 0.f;
    for (int d = lane; d < DIM; d += 32) {
        float xv = xr[d];
        xo[d] = __float2half_rn(xv);
        const float4* g4 = reinterpret_cast<const float4*>(gw + (size_t)d * NEXP);
        float4 g0 = g4[0], g1 = g4[1];
        acc[0] += xv * g0.x; acc[1] += xv * g0.y; acc[2] += xv * g0.z; acc[3] += xv * g0.w;
        acc[4] += xv * g1.x; acc[5] += xv * g1.y; acc[6] += xv * g1.z; acc[7] += xv * g1.w;
    }
#pragma unroll
    for (int e = 0; e < NEXP; e++) {
#pragma unroll
        for (int o = 16; o > 0; o >>= 1) acc[e] += __shfl_xor_sync(0xffffffffu, acc[e], o);
    }
    if (lane == 0) {
        int best = 0; float bv = acc[0] + gb[0];
#pragma unroll
        for (int e = 1; e < NEXP; e++) {
            float v = acc[e] + gb[e];
            if (v > bv) { bv = v; best = e; }
        }
        g_top1[tok] = best;
    }
}

// ===================== launch 1: histogram + scan (1 block) =====================
__global__ void hist_kernel() {
    __shared__ int cnt[NEXP];
    const int tid = threadIdx.x;
    if (tid < NEXP) cnt[tid] = 0;
    __syncthreads();
    int local[NEXP];
#pragma unroll
    for (int e = 0; e < NEXP; e++) local[e] = 0;
    for (int i = tid; i < NTOK; i += 1024) {
        int v = g_top1[i];
#pragma unroll
        for (int e = 0; e < NEXP; e++) local[e] += (v == e);
    }
#pragma unroll
    for (int e = 0; e < NEXP; e++) {
#pragma unroll
        for (int o = 16; o > 0; o >>= 1) local[e] += __shfl_xor_sync(0xffffffffu, local[e], o);
        if ((tid & 31) == 0 && local[e]) atomicAdd(&cnt[e], local[e]);
    }
    __syncthreads();
    if (tid == 0) {
        int off = 0;
        for (int e = 0; e < NEXP; e++) { g_off[e] = off; g_cnt[e] = cnt[e]; off += cnt[e]; }
    }
    if (tid < NEXP) g_cnt2[tid] = 0;
}

// ===================== launch 2: scatter fused with conv_w2 =====================
// blocks [0,32): scatter; blocks [32, 32+32768): conv_w2 tiles
__global__ __launch_bounds__(256)
void scatter_convw2_kernel(const float* __restrict__ w2) {
    const int b = blockIdx.x;
    if (b >= 32) {
        int cb = b - 32;
        int e  = cb >> 12;
        int r  = cb & 4095;
        int c0 = (r & 31) * 32;            // DIM tile col
        int r0 = (r >> 5) * 32;            // HID tile row
        conv_tile(w2, g_w2, HID, DIM, e, r0, c0);
        return;
    }
    int n = b * 256 + threadIdx.x;
    int e = g_top1[n];
    int p = atomicAdd(&g_cnt2[e], 1);
    g_perm[g_off[e] + p] = n;
}

// ===================== GEMM core: CTA 128x128, 4 warps 2x2, warp tile 64x64 =====================
// Single __syncthreads per K-chunk: loads for chunk i+2 are issued AFTER the
// barrier that follows chunk i's arrival. Passing barrier i implies all warps
// completed chunk i-1's MMAs, so overwriting stage (i+2)%3 == (i-1)%3 is safe.
#define AOFF 0
#define BOFF 16384
#define STAGE 32768
#define NSTAGE 3

template<bool FIRST>
__global__ __launch_bounds__(128, 2)
void moe_gemm(const float* __restrict__ bias,
              const float* __restrict__ x,
              float* __restrict__ out) {
    constexpr int KDIM = FIRST ? DIM : HID;
    constexpr int NDIM = FIRST ? HID : DIM;
    constexpr int NKC  = KDIM / 64;

    const int e  = blockIdx.z;
    const int Me = g_cnt[e];
    const int m0 = blockIdx.y * 128;
    if (m0 >= Me) return;
    const int off = g_off[e];
    const int n0  = blockIdx.x * 128;

    const __half* A = FIRST ? g_x16 : g_h;
    const __half* W = (FIRST ? g_w1 : g_w2) + (size_t)e * NDIM * KDIM;

    extern __shared__ char smem[];
    const uint32_t sb = smem_u32(smem);
    __shared__ int s_perm[128];

    const int tid  = threadIdx.x;
    const int lane = tid & 31;
    const int wid  = tid >> 5;
    const int wrow = wid & 1;
    const int wcol = wid >> 1;

    {
        int r = m0 + tid;
        if (r >= Me) r = Me - 1;
        s_perm[tid] = g_perm[off + r];
    }
    __syncthreads();

    auto issue_loads = [&](int chunk) {
        const uint32_t base = sb + (chunk % NSTAGE) * STAGE;
        const int k0 = chunk * 64;
#pragma unroll
        for (int w = 0; w < 8; w++) {
            int idx = w * 128 + tid;
            int row = idx >> 3;
            int c8  = idx & 7;
            uint32_t sw = (uint32_t)(row * 128 + ((c8 * 16) ^ ((row & 7) << 4)));
            const __half* asrc;
            if (FIRST) asrc = A + (size_t)s_perm[row] * KDIM + k0 + c8 * 8;
            else       asrc = A + (size_t)(off + m0 + row) * KDIM + k0 + c8 * 8;
            cp16(base + AOFF + sw, asrc);
            cp16(base + BOFF + sw, W + (size_t)(n0 + row) * KDIM + k0 + c8 * 8);
        }
    };

    const int sel = lane >> 3;
    const int l7  = lane & 7;
    const uint32_t lxor = (uint32_t)(l7 << 4);
    uint32_t arow[4], brow[4];
#pragma unroll
    for (int mf = 0; mf < 4; mf++)
        arow[mf] = (uint32_t)((wrow * 64 + mf * 16 + (sel & 1) * 8 + l7) * 128);
#pragma unroll
    for (int nb = 0; nb < 4; nb++)
        brow[nb] = (uint32_t)((wcol * 64 + nb * 16 + (sel >> 1) * 8 + l7) * 128);
    const uint32_t acb = (uint32_t)((sel >> 1) * 16);
    const uint32_t bcb = (uint32_t)((sel & 1) * 16);

    float c[4][8][4];
#pragma unroll
    for (int i = 0; i < 4; i++)
#pragma unroll
        for (int j = 0; j < 8; j++)
#pragma unroll
            for (int r = 0; r < 4; r++) c[i][j][r] = 0.f;

    issue_loads(0); CP_COMMIT();
    issue_loads(1); CP_COMMIT();

#pragma unroll 1
    for (int i = 0; i < NKC; i++) {
        // pending groups entering here: chunks i..min(i+1, NKC-1)
        if (i < NKC - 1) { CP_WAIT1(); } else { CP_WAIT0(); }
        __syncthreads();                         // single barrier per chunk
        if (i + 2 < NKC) { issue_loads(i + 2); CP_COMMIT(); }

        const uint32_t base = sb + (i % NSTAGE) * STAGE;
#pragma unroll
        for (int kk = 0; kk < 4; kk++) {
            const uint32_t colA = (acb + kk * 32) ^ lxor;
            const uint32_t colB = (bcb + kk * 32) ^ lxor;

            uint32_t Af[4][4], Bf[4][4];
#pragma unroll
            for (int mf = 0; mf < 4; mf++)
                ldsm4(Af[mf][0], Af[mf][1], Af[mf][2], Af[mf][3], base + AOFF + arow[mf] + colA);
#pragma unroll
            for (int nb = 0; nb < 4; nb++)
                ldsm4(Bf[nb][0], Bf[nb][1], Bf[nb][2], Bf[nb][3], base + BOFF + brow[nb] + colB);
#pragma unroll
            for (int mf = 0; mf < 4; mf++)
#pragma unroll
                for (int nb = 0; nb < 4; nb++)
#pragma unroll
                    for (int h = 0; h < 2; h++)
                        mma16816(c[mf][nb*2+h][0], c[mf][nb*2+h][1], c[mf][nb*2+h][2], c[mf][nb*2+h][3],
                                 Af[mf][0], Af[mf][1], Af[mf][2], Af[mf][3],
                                 Bf[nb][2*h], Bf[nb][2*h+1]);
        }
    }

    const int gr = lane >> 2;
    const int gc = (lane & 3) * 2;
    const float* bs = bias + (size_t)e * NDIM;

#pragma unroll
    for (int mf = 0; mf < 4; mf++) {
#pragma unroll
        for (int half = 0; half < 2; half++) {
            const int ml = wrow * 64 + mf * 16 + half * 8 + gr;
            if (m0 + ml >= Me) continue;
            const int slot = off + m0 + ml;
#pragma unroll
            for (int nf = 0; nf < 8; nf++) {
                const int n = n0 + wcol * 64 + nf * 8 + gc;
                const float2 bv = *reinterpret_cast<const float2*>(bs + n);
                float v0 = c[mf][nf][half * 2 + 0] + bv.x;
                float v1 = c[mf][nf][half * 2 + 1] + bv.y;
                if (FIRST) {
                    v0 = fmaxf(v0, 0.f);
                    v1 = fmaxf(v1, 0.f);
                    *reinterpret_cast<__half2*>(g_h + (size_t)slot * HID + n) =
                        __half2(__float2half_rn(v0), __float2half_rn(v1));
                } else {
                    const int tok = s_perm[ml];
                    const float2 xv = *reinterpret_cast<const float2*>(x + (size_t)tok * DIM + n);
                    float2 ov = make_float2(v0 + xv.x, v1 + xv.y);
                    *reinterpret_cast<float2*>(out + (size_t)tok * DIM + n) = ov;
                }
            }
        }
    }
}

// ===================== launch =====================
extern "C" void kernel_launch(void* const* d_in, const int* in_sizes, int n_in,
                              void* d_out, int out_size) {
    const float* x  = (const float*)d_in[0];
    const float* gw = (const float*)d_in[1];
    const float* gb = (const float*)d_in[2];
    const float* w1 = (const float*)d_in[3];
    const float* b1 = (const float*)d_in[4];
    const float* w2 = (const float*)d_in[5];
    const float* b2 = (const float*)d_in[6];
    float* out = (float*)d_out;

    const int SMEM_BYTES = NSTAGE * STAGE;   // 96KB -> 2 CTAs/SM
    cudaFuncSetAttribute(moe_gemm<true>,  cudaFuncAttributeMaxDynamicSharedMemorySize, SMEM_BYTES);
    cudaFuncSetAttribute(moe_gemm<false>, cudaFuncAttributeMaxDynamicSharedMemorySize, SMEM_BYTES);

    // launch 0: gate + conv_w1 (independent blocks, run concurrently)
    gate_convw1_kernel<<<1024 + 32768, 256>>>(x, gw, gb, w1);
    // launch 1: histogram + scan
    hist_kernel<<<1, 1024>>>();
    // launch 2: scatter + conv_w2
    scatter_convw2_kernel<<<32 + 32768, 256>>>(w2);
    // launch 3: GEMM1
    moe_gemm<true ><<<dim3(HID / 128, NTOK / 128, NEXP), 128, SMEM_BYTES>>>(b1, x, nullptr);
    // launch 4: GEMM2
    moe_gemm<false><<<dim3(DIM / 128, NTOK / 128, NEXP), 128, SMEM_BYTES>>>(b2, x, out);
}